// round 9
// baseline (speedup 1.0000x reference)
#include <cuda_runtime.h>
#include <cuda_bf16.h>

#define MAX_NODES 1048576
__device__ float g_nodecol[MAX_NODES];   // packed nodes[:,0], rebuilt every launch

// Seed out[i] = w_node*nodes[i,0] + b_node and pack nodes[:,0] into g_nodecol.
// 4 nodes per thread, loads front-batched for MLP=4 (this pass is pure
// DRAM-latency-bound: strided 32B-sector reads, one per node).
__global__ __launch_bounds__(256)
void tmp_init_kernel(const float* __restrict__ nodes,
                     const float* __restrict__ w_node_p,
                     const float* __restrict__ b_node_p,
                     float* __restrict__ out,
                     int n_nodes, int d_node) {
    const float wn = __ldg(w_node_p);
    const float bn = __ldg(b_node_p);

    int i0 = (blockIdx.x * blockDim.x + threadIdx.x) * 4;

    if (i0 + 3 < n_nodes) {
        // Four independent strided loads, all in flight together.
        float v0 = __ldg(nodes + (size_t)(i0 + 0) * d_node);
        float v1 = __ldg(nodes + (size_t)(i0 + 1) * d_node);
        float v2 = __ldg(nodes + (size_t)(i0 + 2) * d_node);
        float v3 = __ldg(nodes + (size_t)(i0 + 3) * d_node);

        // Packed column: contiguous float4 store.
        *(float4*)(g_nodecol + i0) = make_float4(v0, v1, v2, v3);
        // Seeded output: contiguous float4 store.
        float4 o = make_float4(fmaf(wn, v0, bn), fmaf(wn, v1, bn),
                               fmaf(wn, v2, bn), fmaf(wn, v3, bn));
        *(float4*)(out + i0) = o;
    } else {
        for (int i = i0; i < n_nodes; ++i) {
            float v = __ldg(nodes + (size_t)i * d_node);
            g_nodecol[i] = v;
            out[i] = fmaf(wn, v, bn);
        }
    }
}

// Warp-cooperative: each warp handles 32 consecutive edges.
// Edge rows read as 4 coalesced float4 sweeps (2KB/warp, evict-first);
// element 0 redistributed via shfl. Sender gather hits the packed 400KB
// g_nodecol (dense, L1/L2-resident). Safe to __ldg: g_nodecol is written
// only by the init kernel and L1 is flushed at launch boundaries.
__global__ __launch_bounds__(256)
void tmp_edge_kernel(const float* __restrict__ edges,
                     const int*   __restrict__ senders,
                     const int*   __restrict__ receivers,
                     const float* __restrict__ w_node_p,
                     const float* __restrict__ w_edge_p,
                     float* __restrict__ out,
                     int n_edges, int d_edge) {
    const float wn = __ldg(w_node_p);
    const float we = __ldg(w_edge_p);

    const int tid         = blockIdx.x * blockDim.x + threadIdx.x;
    const int warp_global = tid >> 5;
    const int lane        = tid & 31;
    const int base        = warp_global * 32;

    if (base >= n_edges) return;

    if (base + 32 <= n_edges && d_edge == 16) {
        // Coalesced index loads: one edge per lane.
        const int e = base + lane;
        const int s = __ldcs(senders + e);
        const int r = __ldcs(receivers + e);

        // 4 coalesced float4 sweeps over the warp's 2KB of edge rows.
        const float4* ef4 = (const float4*)edges;
        const size_t f4base = (size_t)base * 4;
        float4 q0 = __ldcs(ef4 + f4base + 0 * 32 + lane);
        float4 q1 = __ldcs(ef4 + f4base + 1 * 32 + lane);
        float4 q2 = __ldcs(ef4 + f4base + 2 * 32 + lane);
        float4 q3 = __ldcs(ef4 + f4base + 3 * 32 + lane);

        // Gather from the packed column via the read-only path.
        const float nv = __ldg(&g_nodecol[s]);

        // Lane L wants edge base+L: sweep L/8, source lane (L%8)*4, comp .x.
        const int src = (lane & 7) * 4;
        float t0 = __shfl_sync(0xffffffffu, q0.x, src);
        float t1 = __shfl_sync(0xffffffffu, q1.x, src);
        float t2 = __shfl_sync(0xffffffffu, q2.x, src);
        float t3 = __shfl_sync(0xffffffffu, q3.x, src);
        const int sel = lane >> 3;
        float ev = (sel == 0) ? t0 : (sel == 1) ? t1 : (sel == 2) ? t2 : t3;

        atomicAdd(out + r, fmaf(we, ev, wn * nv));
    } else {
        // Tail / generic path
        const int e = base + lane;
        if (e < n_edges) {
            const int s = __ldg(senders + e);
            const int r = __ldg(receivers + e);
            const float ev = __ldg(edges + (size_t)e * d_edge);
            const float nv = __ldg(&g_nodecol[s]);
            atomicAdd(out + r, fmaf(we, ev, wn * nv));
        }
    }
}

extern "C" void kernel_launch(void* const* d_in, const int* in_sizes, int n_in,
                              void* d_out, int out_size) {
    const float* nodes     = (const float*)d_in[0];
    const float* edges     = (const float*)d_in[1];
    const int*   senders   = (const int*)  d_in[2];
    const int*   receivers = (const int*)  d_in[3];
    const float* w_node    = (const float*)d_in[4];
    const float* w_edge    = (const float*)d_in[5];
    const float* b_node    = (const float*)d_in[6];
    float*       out       = (float*)d_out;

    const int n_nodes = out_size;
    const int n_edges = in_sizes[2];
    const int d_node  = in_sizes[0] / n_nodes;   // 128
    const int d_edge  = in_sizes[1] / n_edges;   // 16

    // 1) Seed output and pack nodes[:,0] (4 nodes/thread).
    {
        int threads = 256;
        int blocks  = (n_nodes + threads * 4 - 1) / (threads * 4);
        tmp_init_kernel<<<blocks, threads>>>(nodes, w_node, b_node, out, n_nodes, d_node);
    }

    // 2) Scatter-add messages (32 edges per warp, warp-cooperative).
    {
        int threads = 256;                        // 8 warps/block
        int edges_per_block = (threads / 32) * 32;
        int blocks = (n_edges + edges_per_block - 1) / edges_per_block;
        tmp_edge_kernel<<<blocks, threads>>>(edges, senders, receivers,
                                             w_node, w_edge, out,
                                             n_edges, d_edge);
    }
}

// round 11
// speedup vs baseline: 1.0377x; 1.0377x over previous
#include <cuda_runtime.h>
#include <cuda_bf16.h>

// K1: zero the accumulator (out is poisoned by the harness).
__global__ __launch_bounds__(256)
void tmp_zero_kernel(float* __restrict__ out, int n_nodes) {
    int i = blockIdx.x * blockDim.x + threadIdx.x;
    if (i < n_nodes) out[i] = 0.0f;
}

// K2: fused seed + edge scatter. All writes to out are atomic, so the two
// roles need no ordering between them.
//  - Seed blocks (bid < seed_blocks): atomicAdd(out+i, wn*nodes[i,0] + bn).
//    Scheduled first so wave 1 pulls all of nodes[:,0]'s 64B sectors into L2
//    before the bulk of the edge gathers arrive.
//  - Edge blocks: warp-cooperative, 32 edges/warp. Edge rows read as 4
//    coalesced float4 sweeps (evict-first streaming); element 0 redistributed
//    via shfl. Sender gather reads nodes[s,0] (sectors L2-resident after the
//    seed sweep). Receiver scatter via fire-and-forget atomicAdd (REDG).
__global__ __launch_bounds__(256)
void tmp_fused_kernel(const float* __restrict__ nodes,
                      const float* __restrict__ edges,
                      const int*   __restrict__ senders,
                      const int*   __restrict__ receivers,
                      const float* __restrict__ w_node_p,
                      const float* __restrict__ w_edge_p,
                      const float* __restrict__ b_node_p,
                      float* __restrict__ out,
                      int n_nodes, int n_edges, int d_node, int d_edge,
                      int seed_blocks) {
    const float wn = __ldg(w_node_p);
    const float we = __ldg(w_edge_p);

    if (blockIdx.x < (unsigned)seed_blocks) {
        // ---- Seed role ----
        const float bn = __ldg(b_node_p);
        int i = blockIdx.x * blockDim.x + threadIdx.x;
        if (i < n_nodes) {
            float v = __ldg(nodes + (size_t)i * d_node);
            atomicAdd(out + i, fmaf(wn, v, bn));
        }
        return;
    }

    // ---- Edge role ----
    const int ebid        = blockIdx.x - seed_blocks;
    const int etid        = ebid * blockDim.x + threadIdx.x;
    const int warp_global = etid >> 5;
    const int lane        = etid & 31;
    const int base        = warp_global * 32;

    if (base >= n_edges) return;

    if (base + 32 <= n_edges && d_edge == 16) {
        // Coalesced index loads: one edge per lane.
        const int e = base + lane;
        const int s = __ldcs(senders + e);
        const int r = __ldcs(receivers + e);

        // 4 coalesced float4 sweeps over the warp's 2KB of edge rows.
        const float4* ef4 = (const float4*)edges;
        const size_t f4base = (size_t)base * 4;
        float4 q0 = __ldcs(ef4 + f4base + 0 * 32 + lane);
        float4 q1 = __ldcs(ef4 + f4base + 1 * 32 + lane);
        float4 q2 = __ldcs(ef4 + f4base + 2 * 32 + lane);
        float4 q3 = __ldcs(ef4 + f4base + 3 * 32 + lane);

        // Sender gather: strided, but its 6.4MB sector set is L2-resident
        // (warmed by the seed blocks in wave 1).
        const float nv = __ldg(nodes + (size_t)s * d_node);

        // Lane L wants edge base+L: sweep L/8, source lane (L%8)*4, comp .x.
        const int src = (lane & 7) * 4;
        float t0 = __shfl_sync(0xffffffffu, q0.x, src);
        float t1 = __shfl_sync(0xffffffffu, q1.x, src);
        float t2 = __shfl_sync(0xffffffffu, q2.x, src);
        float t3 = __shfl_sync(0xffffffffu, q3.x, src);
        const int sel = lane >> 3;
        float ev = (sel == 0) ? t0 : (sel == 1) ? t1 : (sel == 2) ? t2 : t3;

        atomicAdd(out + r, fmaf(we, ev, wn * nv));
    } else {
        // Tail / generic path
        const int e = base + lane;
        if (e < n_edges) {
            const int s = __ldg(senders + e);
            const int r = __ldg(receivers + e);
            const float ev = __ldg(edges + (size_t)e * d_edge);
            const float nv = __ldg(nodes + (size_t)s * d_node);
            atomicAdd(out + r, fmaf(we, ev, wn * nv));
        }
    }
}

extern "C" void kernel_launch(void* const* d_in, const int* in_sizes, int n_in,
                              void* d_out, int out_size) {
    const float* nodes     = (const float*)d_in[0];
    const float* edges     = (const float*)d_in[1];
    const int*   senders   = (const int*)  d_in[2];
    const int*   receivers = (const int*)  d_in[3];
    const float* w_node    = (const float*)d_in[4];
    const float* w_edge    = (const float*)d_in[5];
    const float* b_node    = (const float*)d_in[6];
    float*       out       = (float*)d_out;

    const int n_nodes = out_size;
    const int n_edges = in_sizes[2];
    const int d_node  = in_sizes[0] / n_nodes;   // 128
    const int d_edge  = in_sizes[1] / n_edges;   // 16

    const int threads = 256;

    // K1: zero the accumulator.
    {
        int blocks = (n_nodes + threads - 1) / threads;
        tmp_zero_kernel<<<blocks, threads>>>(out, n_nodes);
    }

    // K2: fused seed + edge scatter.
    {
        int seed_blocks = (n_nodes + threads - 1) / threads;            // 391
        int edges_per_block = (threads / 32) * 32;                      // 256
        int edge_blocks = (n_edges + edges_per_block - 1) / edges_per_block; // 12500
        tmp_fused_kernel<<<seed_blocks + edge_blocks, threads>>>(
            nodes, edges, senders, receivers,
            w_node, w_edge, b_node, out,
            n_nodes, n_edges, d_node, d_edge, seed_blocks);
    }
}